// round 4
// baseline (speedup 1.0000x reference)
#include <cuda_runtime.h>

// DotProductAttention_300647710747
// inp: (B=4, C=80, H=512, W=512) f32, channels = [q(8) | k(8x8) | v(8)]
// out: (B=4, 8, H, W) f32
// R4: 1 pixel/thread (scalar, coalesced), occupancy capped to 20 warps/SM via
// 40KB unused dynamic smem -> shrinks drain-tail loss (resident/total) from
// 0.29 to 0.078. No reg cap (let ptxas batch loads), no .cs hints.

#define NK 8
#define NV 8
#define CTOT 80            // NK + NK*NV + NV
#define B_DIM 4
#define PLANE 262144       // 512*512 floats per channel plane

__global__ __launch_bounds__(128)
void dpa_kernel(const float* __restrict__ in, float* __restrict__ out)
{
    extern __shared__ float occupancy_pad[];  // unused; caps blocks/SM
    // keep the compiler from deleting the smem requirement
    if (blockIdx.x == 0xFFFFFFFFu) occupancy_pad[threadIdx.x] = 0.f;

    const int t = blockIdx.x * blockDim.x + threadIdx.x;  // 0 .. B*PLANE-1
    const int b = t >> 18;            // PLANE = 2^18
    const int p = t & (PLANE - 1);

    const float* base = in + (size_t)b * CTOT * PLANE + p;

    float acc[NV];
#pragma unroll
    for (int v = 0; v < NV; v++) acc[v] = 0.f;

#pragma unroll
    for (int kk = 0; kk < NK; kk++) {
        const float q = base[(size_t)kk * PLANE];
#pragma unroll
        for (int v = 0; v < NV; v++) {
            const float kv = base[(size_t)(NK + kk * NV + v) * PLANE];
            acc[v] = fmaf(q, kv, acc[v]);
        }
    }

    // Issue V loads early (independent of softmax) to overlap exp latency.
    float vv[NV];
#pragma unroll
    for (int v = 0; v < NV; v++)
        vv[v] = base[(size_t)(NK + NK * NV + v) * PLANE];

    const float scale = 0.3535533905932738f;  // 1/sqrt(8)
    float m = acc[0] * scale;
#pragma unroll
    for (int v = 0; v < NV; v++) {
        acc[v] *= scale;
        m = fmaxf(m, acc[v]);
    }
    float s = 0.f;
#pragma unroll
    for (int v = 0; v < NV; v++) {
        acc[v] = __expf(acc[v] - m);
        s += acc[v];
    }
    const float rs = 1.f / s;

    float* ob = out + (size_t)b * NV * PLANE + p;
#pragma unroll
    for (int v = 0; v < NV; v++)
        ob[(size_t)v * PLANE] = acc[v] * rs * vv[v];
}

extern "C" void kernel_launch(void* const* d_in, const int* in_sizes, int n_in,
                              void* d_out, int out_size)
{
    const float* in_p = (const float*)d_in[0];
    float* out_p = (float*)d_out;
    const int nthreads = B_DIM * PLANE;       // 1048576
    const int block = 128;
    const size_t smem = 40 * 1024;            // cap: 5 blocks (20 warps) per SM
    dpa_kernel<<<nthreads / block, block, smem>>>(in_p, out_p);
}